// round 6
// baseline (speedup 1.0000x reference)
#include <cuda_runtime.h>
#include <cstdint>
#include <cstddef>

// x_{t+1} = x_t + 0.1*tanh([x_t,u_t]@W1 + b1)@W2 + b2
// B=1024, T=200, SD=64, CD=32, H=512.
// 128 persistent CTAs x 512 threads (16 warps), 8 batch rows packed as 4
// f32x2 row-pairs. Intra-warp k-split + shfl reduction to minimize l1tex
// wavefronts. Phase A warp w produces exactly the h-strip phase B warp w
// consumes -> no barrier between phases.

typedef unsigned long long u64;

static constexpr int   TSTEPS = 200;
static constexpr int   SDIM   = 64;
static constexpr int   CDIM   = 32;
static constexpr int   HDIM   = 512;
static constexpr int   ROWS   = 8;
static constexpr int   NBLK   = 1024 / ROWS;   // 128
static constexpr int   NTHR   = 512;
static constexpr float DTC    = 0.1f;
static constexpr int   OSTRIDE = (TSTEPS + 1) * SDIM;

static constexpr int W2_STRIDE = 34;                 // u64 per k-row (32 pairs + pad)
static constexpr int W2_U = HDIM * W2_STRIDE;        // 17408
static constexpr int H_U  = 16 * 128;                //  2048 (16 strips x 128)
static constexpr int IN_U = 24 * 16;                 //   384 ([ko24][kg4][rp4])
static constexpr int PS_STRIDE = 258;
static constexpr int PS_U = 16 * PS_STRIDE;          //  4128
static constexpr int B2_U = 64;
static constexpr size_t SMEM_BYTES =
    (size_t)(W2_U + H_U + IN_U + PS_U + B2_U) * 8;   // 192,256 B

__device__ __forceinline__ u64 ffma2(u64 a, u64 b, u64 c) {
    u64 d;
    asm("fma.rn.f32x2 %0, %1, %2, %3;" : "=l"(d) : "l"(a), "l"(b), "l"(c));
    return d;
}
__device__ __forceinline__ u64 fadd2(u64 a, u64 b) {
    u64 d;
    asm("add.rn.f32x2 %0, %1, %2;" : "=l"(d) : "l"(a), "l"(b));
    return d;
}
__device__ __forceinline__ u64 pack2(float lo, float hi) {
    u64 d;
    asm("mov.b64 %0, {%1, %2};" : "=l"(d) : "r"(__float_as_int(lo)), "r"(__float_as_int(hi)));
    return d;
}
__device__ __forceinline__ u64 dupf(float f) {
    u64 d;
    asm("mov.b64 %0, {%1, %1};" : "=l"(d) : "r"(__float_as_int(f)));
    return d;
}
__device__ __forceinline__ float2 unpack2(u64 d) {
    int lo, hi;
    asm("mov.b64 {%0, %1}, %2;" : "=r"(lo), "=r"(hi) : "l"(d));
    return make_float2(__int_as_float(lo), __int_as_float(hi));
}
__device__ __forceinline__ u64 shflx64(u64 v, int m) {
    return __shfl_xor_sync(0xffffffffu, v, m);
}
__device__ __forceinline__ float fast_tanh(float x) {
    float e = __expf(2.0f * x);
    return 1.0f - __fdividef(2.0f, e + 1.0f);
}
// in_s layout: [ko][kg][rp], k = kg*24 + ko
__device__ __forceinline__ int inIdx(int k, int rp) {
    return (k % 24) * 16 + (k / 24) * 4 + rp;
}

__global__ void __launch_bounds__(NTHR, 1)
rollout_kernel(const float* __restrict__ x0,
               const float* __restrict__ controls,
               const float* __restrict__ W1,
               const float* __restrict__ b1,
               const float* __restrict__ W2,
               const float* __restrict__ b2,
               float* __restrict__ out)
{
    extern __shared__ u64 sm[];
    u64* W2p  = sm;              // [k][34] pairs {W2[k][2i],W2[k][2i+1]}
    u64* h_s  = W2p + W2_U;      // 16 strips x 128: strip w = H cols w*32..+31
    u64* in_s = h_s + H_U;       // [ko][kg][rp]
    u64* psd  = in_s + IN_U;     // [w][258]: (i*4+rp)
    u64* b2d  = psd + PS_U;      // dup'd b2

    const int tid  = threadIdx.x;
    const int lane = tid & 31;
    const int w    = tid >> 5;
    const int b0   = blockIdx.x * ROWS;

    // Phase A mapping
    const int kgA  = lane >> 3;          // 0..3 (24 k each)
    const int cq   = lane & 7;           // col quad
    const int cbase = w * 32 + cq * 4;   // 4 cols cbase..cbase+3
    const int kgA4 = kgA * 4;
    // Phase B mapping
    const int kgB  = lane >> 4;          // 0..1 (16 k each)
    const int ipq  = lane & 15;          // i = ipq*4 + ii, ii 0..3

    // ---- prologue ----
    for (int idx = tid; idx < HDIM * 32; idx += NTHR) {
        int k = idx >> 5, ip = idx & 31;
        W2p[k * W2_STRIDE + ip] = *(const u64*)&W2[k * SDIM + 2 * ip];
    }
    if (tid < SDIM) b2d[tid] = dupf(b2[tid]);
    if (tid < 256) {   // x0 row-paired into in_s
        int i = tid >> 2, rp = tid & 3;
        float a = x0[(b0 + 2 * rp) * SDIM + i];
        float b = x0[(b0 + 2 * rp + 1) * SDIM + i];
        in_s[inIdx(i, rp)] = pack2(a, b);
    }
    if (tid < 128) {   // u(0)
        int rp = tid >> 5, j = lane;
        float a = controls[(size_t)(b0 + 2 * rp) * TSTEPS * CDIM + j];
        float b = controls[(size_t)(b0 + 2 * rp + 1) * TSTEPS * CDIM + j];
        in_s[inIdx(SDIM + j, rp)] = pack2(a, b);
    }
    {   // states[:,0,:]
        int r = tid >> 6, i = tid & 63;
        out[(size_t)(b0 + r) * OSTRIDE + i] = x0[(b0 + r) * SDIM + i];
    }

    const u64 b1dup = dupf(b1[cbase + kgA]);
    const u64 dtdup = dupf(DTC);

    // h store address for this lane's column (col c = cbase + kgA)
    const int klA   = (cbase + kgA) & 31;
    const int hstAdr = w * 128 + (klA & 15) * 8 + (klA >> 4) * 4;
    // Phase B bases
    const int hldAdr = w * 128 + kgB * 4;
    const int w2Adr  = (w * 32 + kgB * 16) * W2_STRIDE + ipq * 2;
    const int psAdr  = w * PS_STRIDE + (ipq * 4 + kgB * 2) * 4;

    // W1 stream buffers: 4 chunks of 6 ko; preload chunk 0
    float4 wbuf[2][6];
    #pragma unroll
    for (int j = 0; j < 6; ++j)
        wbuf[0][j] = *(const float4*)&W1[(kgA * 24 + j) * HDIM + cbase];

    __syncthreads();

    for (int t = 0; t < TSTEPS; ++t) {
        // prefetch next-step controls
        float un0 = 0.0f, un1 = 0.0f;
        if (tid < 128 && t + 1 < TSTEPS) {
            int rp = tid >> 5;
            un0 = controls[(size_t)(b0 + 2 * rp) * TSTEPS * CDIM
                           + (size_t)(t + 1) * CDIM + lane];
            un1 = controls[(size_t)(b0 + 2 * rp + 1) * TSTEPS * CDIM
                           + (size_t)(t + 1) * CDIM + lane];
        }

        // ---- Phase A: partial dot over this lane's 24 k, 4 cols x 4 rp ----
        u64 acc[16];
        #pragma unroll
        for (int q = 0; q < 16; ++q) acc[q] = 0ull;

        #pragma unroll
        for (int blk = 0; blk < 4; ++blk) {
            const int cur = blk & 1;
            const int kpf = ((blk + 1) & 3) * 6;   // chunk to prefetch
            #pragma unroll
            for (int j = 0; j < 6; ++j)
                wbuf[cur ^ 1][j] =
                    *(const float4*)&W1[(kgA * 24 + kpf + j) * HDIM + cbase];
            #pragma unroll
            for (int j = 0; j < 6; ++j) {
                const int ko = blk * 6 + j;
                ulonglong2 u01 = *(const ulonglong2*)&in_s[ko * 16 + kgA4];
                ulonglong2 u23 = *(const ulonglong2*)&in_s[ko * 16 + kgA4 + 2];
                float4 wq = wbuf[cur][j];
                u64 w0 = dupf(wq.x), w1 = dupf(wq.y);
                u64 w2v = dupf(wq.z), w3 = dupf(wq.w);
                acc[0]  = ffma2(u01.x, w0, acc[0]);
                acc[1]  = ffma2(u01.y, w0, acc[1]);
                acc[2]  = ffma2(u23.x, w0, acc[2]);
                acc[3]  = ffma2(u23.y, w0, acc[3]);
                acc[4]  = ffma2(u01.x, w1, acc[4]);
                acc[5]  = ffma2(u01.y, w1, acc[5]);
                acc[6]  = ffma2(u23.x, w1, acc[6]);
                acc[7]  = ffma2(u23.y, w1, acc[7]);
                acc[8]  = ffma2(u01.x, w2v, acc[8]);
                acc[9]  = ffma2(u01.y, w2v, acc[9]);
                acc[10] = ffma2(u23.x, w2v, acc[10]);
                acc[11] = ffma2(u23.y, w2v, acc[11]);
                acc[12] = ffma2(u01.x, w3, acc[12]);
                acc[13] = ffma2(u01.y, w3, acc[13]);
                acc[14] = ffma2(u23.x, w3, acc[14]);
                acc[15] = ffma2(u23.y, w3, acc[15]);
            }
        }
        // butterfly allreduce over the 4 kgA groups (lane bits 3,4)
        #pragma unroll
        for (int q = 0; q < 16; ++q) acc[q] = fadd2(acc[q], shflx64(acc[q], 8));
        #pragma unroll
        for (int q = 0; q < 16; ++q) acc[q] = fadd2(acc[q], shflx64(acc[q], 16));

        // each lane finishes column cc = kgA: +b1, tanh, store to own h-strip
        {
            u64 hv[4];
            #pragma unroll
            for (int rp = 0; rp < 4; ++rp) {
                u64 v01 = (kgA & 1) ? acc[4 + rp] : acc[rp];
                u64 v23 = (kgA & 1) ? acc[12 + rp] : acc[8 + rp];
                u64 v   = (kgA & 2) ? v23 : v01;
                float2 f = unpack2(fadd2(v, b1dup));
                hv[rp] = pack2(fast_tanh(f.x), fast_tanh(f.y));
            }
            *(ulonglong2*)&h_s[hstAdr]     = make_ulonglong2(hv[0], hv[1]);
            *(ulonglong2*)&h_s[hstAdr + 2] = make_ulonglong2(hv[2], hv[3]);
        }
        // no barrier: phase B warp w reads only strip w (written by itself)

        // ---- Phase B: partial over this lane's 16 k, 4 i x 4 rp ----
        u64 aB[16];
        #pragma unroll
        for (int q = 0; q < 16; ++q) aB[q] = 0ull;
        #pragma unroll
        for (int ko = 0; ko < 16; ++ko) {
            ulonglong2 h01 = *(const ulonglong2*)&h_s[hldAdr + ko * 8];
            ulonglong2 h23 = *(const ulonglong2*)&h_s[hldAdr + ko * 8 + 2];
            ulonglong2 wv  = *(const ulonglong2*)&W2p[w2Adr + ko * W2_STRIDE];
            float2 pa = unpack2(wv.x);
            float2 pb = unpack2(wv.y);
            u64 wi0 = dupf(pa.x), wi1 = dupf(pa.y);
            u64 wi2 = dupf(pb.x), wi3 = dupf(pb.y);
            aB[0]  = ffma2(h01.x, wi0, aB[0]);
            aB[1]  = ffma2(h01.y, wi0, aB[1]);
            aB[2]  = ffma2(h23.x, wi0, aB[2]);
            aB[3]  = ffma2(h23.y, wi0, aB[3]);
            aB[4]  = ffma2(h01.x, wi1, aB[4]);
            aB[5]  = ffma2(h01.y, wi1, aB[5]);
            aB[6]  = ffma2(h23.x, wi1, aB[6]);
            aB[7]  = ffma2(h23.y, wi1, aB[7]);
            aB[8]  = ffma2(h01.x, wi2, aB[8]);
            aB[9]  = ffma2(h01.y, wi2, aB[9]);
            aB[10] = ffma2(h23.x, wi2, aB[10]);
            aB[11] = ffma2(h23.y, wi2, aB[11]);
            aB[12] = ffma2(h01.x, wi3, aB[12]);
            aB[13] = ffma2(h01.y, wi3, aB[13]);
            aB[14] = ffma2(h23.x, wi3, aB[14]);
            aB[15] = ffma2(h23.y, wi3, aB[15]);
        }
        // allreduce over kgB (lane bit 4)
        #pragma unroll
        for (int q = 0; q < 16; ++q) aB[q] = fadd2(aB[q], shflx64(aB[q], 16));
        // lane stores ii = kgB*2 + {0,1} (8 consecutive u64)
        {
            u64 st[8];
            #pragma unroll
            for (int q = 0; q < 8; ++q) st[q] = kgB ? aB[8 + q] : aB[q];
            *(ulonglong2*)&psd[psAdr]     = make_ulonglong2(st[0], st[1]);
            *(ulonglong2*)&psd[psAdr + 2] = make_ulonglong2(st[2], st[3]);
            *(ulonglong2*)&psd[psAdr + 4] = make_ulonglong2(st[4], st[5]);
            *(ulonglong2*)&psd[psAdr + 6] = make_ulonglong2(st[6], st[7]);
        }
        __syncthreads();

        // ---- Epilogue: reduce 16 warps, x update, stores ----
        if (tid < 256) {
            const int i = tid >> 2, rp = tid & 3;
            u64 s = psd[tid];
            #pragma unroll
            for (int q = 1; q < 16; ++q)
                s = fadd2(s, psd[q * PS_STRIDE + tid]);
            s = fadd2(s, b2d[i]);
            const int xi = inIdx(i, rp);
            u64 xn = ffma2(dtdup, s, in_s[xi]);
            in_s[xi] = xn;
            float2 xv = unpack2(xn);
            size_t so = (size_t)(t + 1) * SDIM + i;
            out[(size_t)(b0 + 2 * rp) * OSTRIDE + so]     = xv.x;
            out[(size_t)(b0 + 2 * rp + 1) * OSTRIDE + so] = xv.y;
        }
        if (tid < 128 && t + 1 < TSTEPS) {
            int rp = tid >> 5;
            in_s[inIdx(SDIM + lane, rp)] = pack2(un0, un1);
        }
        __syncthreads();
    }
}

extern "C" void kernel_launch(void* const* d_in, const int* in_sizes, int n_in,
                              void* d_out, int out_size) {
    const float* x0       = (const float*)d_in[0];
    const float* controls = (const float*)d_in[1];
    const float* W1       = (const float*)d_in[2];
    const float* b1       = (const float*)d_in[3];
    const float* W2       = (const float*)d_in[4];
    const float* b2       = (const float*)d_in[5];
    float* out = (float*)d_out;

    static bool attr_set = false;
    if (!attr_set) {
        cudaFuncSetAttribute(rollout_kernel,
                             cudaFuncAttributeMaxDynamicSharedMemorySize,
                             (int)SMEM_BYTES);
        attr_set = true;
    }
    rollout_kernel<<<NBLK, NTHR, SMEM_BYTES>>>(x0, controls, W1, b1, W2, b2, out);
}

// round 7
// speedup vs baseline: 1.1173x; 1.1173x over previous
#include <cuda_runtime.h>
#include <cstdint>
#include <cstddef>

// x_{t+1} = x_t + 0.1*tanh([x_t,u_t]@W1 + b1)@W2 + b2
// B=1024, T=200, SD=64, CD=32, H=512.
// 128 persistent CTAs x 512 threads (16 warps). 8 rows packed as 4 f32x2
// row-pairs. Phase A: warp = (col-strip x 8, k-half x 2); k-halves reduced
// through smem hpart (no shfl). Phase B: warp = 32-k strip, lane 2-way
// k-split; W2 half in regs half in smem; one shfl round.

typedef unsigned long long u64;

static constexpr int   TSTEPS = 200;
static constexpr int   SDIM   = 64;
static constexpr int   CDIM   = 32;
static constexpr int   HDIM   = 512;
static constexpr int   ROWS   = 8;
static constexpr int   NBLK   = 1024 / ROWS;   // 128
static constexpr int   NTHR   = 512;
static constexpr float DTC    = 0.1f;
static constexpr int   OSTRIDE = (TSTEPS + 1) * SDIM;

static constexpr int IN_U  = 48 * 8;          //  384: [ko48][kh2][rp4]
static constexpr int HP_U  = 2 * 4 * 512;     // 4096: hpart[kh][rp][col]
static constexpr int HS_U  = 512 * 4 + 64;    // 2112: h[k*4+(k>>4)*2+rp]
static constexpr int W2H_U = 512 * 17;        // 8704: {W2[k][4p+2],W2[k][4p+3]}
static constexpr int PS_U  = 16 * 258;        // 4128: psd[q][rp*64+i]
static constexpr int B2_U  = 64;
static constexpr size_t SMEM_BYTES =
    (size_t)(IN_U + HP_U + HS_U + W2H_U + PS_U + B2_U) * 8;  // 155,904

__device__ __forceinline__ u64 ffma2(u64 a, u64 b, u64 c) {
    u64 d;
    asm("fma.rn.f32x2 %0, %1, %2, %3;" : "=l"(d) : "l"(a), "l"(b), "l"(c));
    return d;
}
__device__ __forceinline__ u64 fadd2(u64 a, u64 b) {
    u64 d;
    asm("add.rn.f32x2 %0, %1, %2;" : "=l"(d) : "l"(a), "l"(b));
    return d;
}
__device__ __forceinline__ u64 pack2(float lo, float hi) {
    u64 d;
    asm("mov.b64 %0, {%1, %2};" : "=l"(d) : "r"(__float_as_int(lo)), "r"(__float_as_int(hi)));
    return d;
}
__device__ __forceinline__ u64 dupf(float f) {
    u64 d;
    asm("mov.b64 %0, {%1, %1};" : "=l"(d) : "r"(__float_as_int(f)));
    return d;
}
__device__ __forceinline__ float2 unpack2(u64 d) {
    int lo, hi;
    asm("mov.b64 {%0, %1}, %2;" : "=r"(lo), "=r"(hi) : "l"(d));
    return make_float2(__int_as_float(lo), __int_as_float(hi));
}
__device__ __forceinline__ u64 shflx64(u64 v, int m) {
    return __shfl_xor_sync(0xffffffffu, v, m);
}
__device__ __forceinline__ float fast_tanh(float x) {
    float e = __expf(2.0f * x);
    return 1.0f - __fdividef(2.0f, e + 1.0f);
}
// in_s: k -> (ko = k%48, kh = k/48): idx = ko*8 + kh*4 + rp
__device__ __forceinline__ int inIdx(int k, int rp) {
    return (k % 48) * 8 + (k / 48) * 4 + rp;
}
// h_s padded index
__device__ __forceinline__ int hsIdx(int k) {
    return k * 4 + (k >> 4) * 2;
}

__global__ void __launch_bounds__(NTHR, 1)
rollout_kernel(const float* __restrict__ x0,
               const float* __restrict__ controls,
               const float* __restrict__ W1,
               const float* __restrict__ b1,
               const float* __restrict__ W2,
               const float* __restrict__ b2,
               float* __restrict__ out)
{
    extern __shared__ u64 sm[];
    u64* in_s  = sm;                 // 384
    u64* hpart = in_s + IN_U;        // [kh][rp][512]
    u64* h_s   = hpart + HP_U;       // padded h
    u64* W2h   = h_s + HS_U;         // [k][17] hi i-pairs
    u64* psd   = W2h + W2H_U;        // [q][258]
    u64* b2d   = psd + PS_U;         // dup'd b2

    const int tid  = threadIdx.x;
    const int lane = tid & 31;
    const int w    = tid >> 5;
    const int b0   = blockIdx.x * ROWS;

    // Phase A warp mapping
    const int kh   = w >> 3;             // k-half 0..1
    const int cs   = w & 7;              // col strip (64 cols)
    const int c0   = cs * 64 + 2 * lane; // even col, owns c0 & c0+1
    const int inb  = kh * 4;
    const int wcol = cs * 32 + lane;     // float2 index in W1 row
    // Phase B mapping
    const int kgB   = lane >> 4;
    const int ipq   = lane & 15;
    const int kbase = w * 32 + kgB * 16;

    // ---- prologue ----
    for (int idx = tid; idx < 8192; idx += NTHR) {
        int k = idx >> 4, p = idx & 15;
        W2h[k * 17 + p] = *(const u64*)&W2[k * SDIM + p * 4 + 2];
    }
    float2 wreg[16];
    #pragma unroll
    for (int ko = 0; ko < 16; ++ko)
        wreg[ko] = *(const float2*)&W2[(kbase + ko) * SDIM + ipq * 4];
    if (tid < SDIM) b2d[tid] = dupf(b2[tid]);
    const u64 b1dup = dupf(b1[tid]);
    const u64 dtdup = dupf(DTC);

    if (tid < 256) {   // x0 row-paired
        int i = tid >> 2, rp = tid & 3;
        in_s[inIdx(i, rp)] = pack2(x0[(b0 + 2 * rp) * SDIM + i],
                                   x0[(b0 + 2 * rp + 1) * SDIM + i]);
    }
    if (tid < 128) {   // u(0): k = 64+lane -> ko=16+lane, kh=1
        int rp = tid >> 5;
        in_s[(16 + lane) * 8 + 4 + rp] =
            pack2(controls[(size_t)(b0 + 2 * rp) * TSTEPS * CDIM + lane],
                  controls[(size_t)(b0 + 2 * rp + 1) * TSTEPS * CDIM + lane]);
    }
    {   // states[:,0,:]
        int r = tid >> 6, i = tid & 63;
        out[(size_t)(b0 + r) * OSTRIDE + i] = x0[(b0 + r) * SDIM + i];
    }

    const float2* W1f2 = (const float2*)W1;   // [k][256]
    float2 wbuf[2][4];
    #pragma unroll
    for (int j = 0; j < 4; ++j)
        wbuf[0][j] = W1f2[(kh * 48 + j) * 256 + wcol];

    __syncthreads();

    for (int t = 0; t < TSTEPS; ++t) {
        // prefetch next-step controls
        float un0 = 0.0f, un1 = 0.0f;
        if (tid < 128 && t + 1 < TSTEPS) {
            int rp = tid >> 5;
            un0 = controls[(size_t)(b0 + 2 * rp) * TSTEPS * CDIM
                           + (size_t)(t + 1) * CDIM + lane];
            un1 = controls[(size_t)(b0 + 2 * rp + 1) * TSTEPS * CDIM
                           + (size_t)(t + 1) * CDIM + lane];
        }

        // ---- Phase A: partial over this warp's 48 k; 2 cols x 4 rp ----
        u64 a[8];
        #pragma unroll
        for (int q = 0; q < 8; ++q) a[q] = 0ull;
        #pragma unroll
        for (int blk = 0; blk < 12; ++blk) {
            const int cur = blk & 1;
            const int kn = ((blk + 1) % 12) * 4;   // wraps to 0 for next step
            #pragma unroll
            for (int j = 0; j < 4; ++j)
                wbuf[cur ^ 1][j] = W1f2[(kh * 48 + kn + j) * 256 + wcol];
            #pragma unroll
            for (int j = 0; j < 4; ++j) {
                const int ko = blk * 4 + j;
                ulonglong2 uA = *(const ulonglong2*)&in_s[ko * 8 + inb];
                ulonglong2 uB = *(const ulonglong2*)&in_s[ko * 8 + inb + 2];
                u64 w0 = dupf(wbuf[cur][j].x);
                u64 w1 = dupf(wbuf[cur][j].y);
                a[0] = ffma2(uA.x, w0, a[0]);
                a[1] = ffma2(uA.y, w0, a[1]);
                a[2] = ffma2(uB.x, w0, a[2]);
                a[3] = ffma2(uB.y, w0, a[3]);
                a[4] = ffma2(uA.x, w1, a[4]);
                a[5] = ffma2(uA.y, w1, a[5]);
                a[6] = ffma2(uB.x, w1, a[6]);
                a[7] = ffma2(uB.y, w1, a[7]);
            }
        }
        #pragma unroll
        for (int rp = 0; rp < 4; ++rp)
            *(ulonglong2*)&hpart[kh * 2048 + rp * 512 + c0] =
                make_ulonglong2(a[rp], a[4 + rp]);
        __syncthreads();

        // ---- Finalize h: sum halves, +b1, tanh; col = tid ----
        {
            u64 hv[4];
            #pragma unroll
            for (int rp = 0; rp < 4; ++rp) {
                u64 s = fadd2(hpart[rp * 512 + tid], hpart[2048 + rp * 512 + tid]);
                float2 f = unpack2(fadd2(s, b1dup));
                hv[rp] = pack2(fast_tanh(f.x), fast_tanh(f.y));
            }
            const int hb = hsIdx(tid);
            *(ulonglong2*)&h_s[hb]     = make_ulonglong2(hv[0], hv[1]);
            *(ulonglong2*)&h_s[hb + 2] = make_ulonglong2(hv[2], hv[3]);
        }
        __syncthreads();

        // ---- Phase B: 16 k per lane-half, 4 i x 4 rp ----
        u64 aB[16];
        #pragma unroll
        for (int q = 0; q < 16; ++q) aB[q] = 0ull;
        #pragma unroll 4
        for (int ko = 0; ko < 16; ++ko) {
            const int k = kbase + ko;
            const int hb = hsIdx(k);
            ulonglong2 hA = *(const ulonglong2*)&h_s[hb];
            ulonglong2 hB = *(const ulonglong2*)&h_s[hb + 2];
            float2 whi = unpack2(W2h[k * 17 + ipq]);
            u64 W0 = dupf(wreg[ko].x), W1v = dupf(wreg[ko].y);
            u64 W2v = dupf(whi.x),     W3v = dupf(whi.y);
            aB[0]  = ffma2(hA.x, W0, aB[0]);
            aB[1]  = ffma2(hA.y, W0, aB[1]);
            aB[2]  = ffma2(hB.x, W0, aB[2]);
            aB[3]  = ffma2(hB.y, W0, aB[3]);
            aB[4]  = ffma2(hA.x, W1v, aB[4]);
            aB[5]  = ffma2(hA.y, W1v, aB[5]);
            aB[6]  = ffma2(hB.x, W1v, aB[6]);
            aB[7]  = ffma2(hB.y, W1v, aB[7]);
            aB[8]  = ffma2(hA.x, W2v, aB[8]);
            aB[9]  = ffma2(hA.y, W2v, aB[9]);
            aB[10] = ffma2(hB.x, W2v, aB[10]);
            aB[11] = ffma2(hB.y, W2v, aB[11]);
            aB[12] = ffma2(hA.x, W3v, aB[12]);
            aB[13] = ffma2(hA.y, W3v, aB[13]);
            aB[14] = ffma2(hB.x, W3v, aB[14]);
            aB[15] = ffma2(hB.y, W3v, aB[15]);
        }
        #pragma unroll
        for (int q = 0; q < 16; ++q) aB[q] = fadd2(aB[q], shflx64(aB[q], 16));
        {   // lane stores its 2 i's (static-index select on kgB)
            const int i0 = ipq * 4 + kgB * 2;
            #pragma unroll
            for (int rp = 0; rp < 4; ++rp) {
                u64 lo = kgB ? aB[8 + rp]  : aB[rp];
                u64 hi = kgB ? aB[12 + rp] : aB[4 + rp];
                *(ulonglong2*)&psd[w * 258 + rp * 64 + i0] =
                    make_ulonglong2(lo, hi);
            }
        }
        __syncthreads();

        // ---- Epilogue ----
        if (tid < 256) {
            const int rp = tid >> 6, i = tid & 63;
            u64 s = psd[rp * 64 + i];
            #pragma unroll
            for (int q = 1; q < 16; ++q)
                s = fadd2(s, psd[q * 258 + rp * 64 + i]);
            s = fadd2(s, b2d[i]);
            const int xi = inIdx(i, rp);
            u64 xn = ffma2(dtdup, s, in_s[xi]);
            in_s[xi] = xn;
            float2 xv = unpack2(xn);
            size_t so = (size_t)(t + 1) * SDIM + i;
            out[(size_t)(b0 + 2 * rp) * OSTRIDE + so]     = xv.x;
            out[(size_t)(b0 + 2 * rp + 1) * OSTRIDE + so] = xv.y;
        }
        if (tid < 128 && t + 1 < TSTEPS) {
            int rp = tid >> 5;
            in_s[(16 + lane) * 8 + 4 + rp] = pack2(un0, un1);
        }
        __syncthreads();
    }
}

extern "C" void kernel_launch(void* const* d_in, const int* in_sizes, int n_in,
                              void* d_out, int out_size) {
    const float* x0       = (const float*)d_in[0];
    const float* controls = (const float*)d_in[1];
    const float* W1       = (const float*)d_in[2];
    const float* b1       = (const float*)d_in[3];
    const float* W2       = (const float*)d_in[4];
    const float* b2       = (const float*)d_in[5];
    float* out = (float*)d_out;

    static bool attr_set = false;
    if (!attr_set) {
        cudaFuncSetAttribute(rollout_kernel,
                             cudaFuncAttributeMaxDynamicSharedMemorySize,
                             (int)SMEM_BYTES);
        attr_set = true;
    }
    rollout_kernel<<<NBLK, NTHR, SMEM_BYTES>>>(x0, controls, W1, b1, W2, b2, out);
}